// round 9
// baseline (speedup 1.0000x reference)
#include <cuda_runtime.h>
#include <cuda_fp16.h>
#include <cstdint>
#include <math.h>

#define BATCH 4
#define TLEN  4096
#define DIM   1024
#define MTOT  (BATCH * TLEN)     // 16384
#define NTOT  (2 * DIM)          // 2048 (z cols | h cols)

// ---------------- scratch (device globals; no allocation allowed) ----------
__device__ __half g_Xh[(size_t)MTOT * DIM];     // [M, 1024] fp16
__device__ __half g_Wf[(size_t)NTOT * DIM];     // [2048 rows: Wz|Wh, 1024] fp16
__device__ __half g_preh[(size_t)MTOT * NTOT];  // z (post-sigmoid) | h_tilde, fp16
#define CHUNK 16
#define NCH   (TLEN / CHUNK)     // 256
__device__ float g_aggA[BATCH * NCH * DIM];
__device__ float g_aggH[BATCH * NCH * DIM];
__device__ float g_carry[BATCH * NCH * DIM];

// ---------------- PTX helpers (compute_103-safe only) ----------------------
__device__ __forceinline__ uint32_t smem_u32(const void* p) {
    uint32_t a;
    asm("{ .reg .u64 t; cvta.to.shared.u64 t, %1; cvt.u32.u64 %0, t; }" : "=r"(a) : "l"(p));
    return a;
}
__device__ __forceinline__ uint32_t sw128(uint32_t o) { return o ^ ((o >> 3) & 0x70); }

__device__ __forceinline__ void cp_async16(uint32_t s, const void* g) {
    asm volatile("cp.async.cg.shared.global [%0], [%1], 16;" :: "r"(s), "l"(g));
}
#define CP_COMMIT() asm volatile("cp.async.commit_group;" ::: "memory")
template <int N> __device__ __forceinline__ void cp_wait() {
    asm volatile("cp.async.wait_group %0;" :: "n"(N) : "memory");
}

#define LDSM_X4(r0, r1, r2, r3, addr) \
    asm volatile("ldmatrix.sync.aligned.m8n8.x4.shared.b16 {%0,%1,%2,%3}, [%4];" \
        : "=r"(r0), "=r"(r1), "=r"(r2), "=r"(r3) : "r"(addr))

#define MMA16816(d, a, b0, b1) \
    asm volatile("mma.sync.aligned.m16n8k16.row.col.f32.f16.f16.f32 " \
        "{%0,%1,%2,%3}, {%4,%5,%6,%7}, {%8,%9}, {%0,%1,%2,%3};" \
        : "+f"((d)[0]), "+f"((d)[1]), "+f"((d)[2]), "+f"((d)[3]) \
        : "r"((a)[0]), "r"((a)[1]), "r"((a)[2]), "r"((a)[3]), "r"(b0), "r"(b1))

// ---------------- conversion kernels ---------------------------------------
__device__ __forceinline__ uint2 pack4h(float a, float b, float c, float d) {
    __half2 p0 = __floats2half2_rn(a, b);
    __half2 p1 = __floats2half2_rn(c, d);
    uint2 r;
    r.x = *reinterpret_cast<uint32_t*>(&p0);
    r.y = *reinterpret_cast<uint32_t*>(&p1);
    return r;
}

__global__ void convert_x_kernel(const float* __restrict__ x) {
    size_t i4 = (size_t)blockIdx.x * blockDim.x + threadIdx.x;
    size_t e = i4 * 4;
    float4 v = *reinterpret_cast<const float4*>(x + e);
    *reinterpret_cast<uint2*>(g_Xh + e) = pack4h(v.x, v.y, v.z, v.w);
}

__global__ void convert_w_kernel(const float* __restrict__ Wz, const float* __restrict__ Wh) {
    size_t i4 = (size_t)blockIdx.x * blockDim.x + threadIdx.x;
    size_t e = i4 * 4;
    const float* src = (e < (size_t)DIM * DIM) ? (Wz + e) : (Wh + (e - (size_t)DIM * DIM));
    float4 v = *reinterpret_cast<const float4*>(src);
    *reinterpret_cast<uint2*>(g_Wf + e) = pack4h(v.x, v.y, v.z, v.w);
}

// ---------------- mma.sync fp16 GEMM ---------------------------------------
// CTA tile 128x128, BK=64, 4 warps (warp tile 64x64), 3-stage cp.async.
// LDS traffic: A dup 2x + B dup 2x = 64KB/iter = 512 cyc < 1024 tensor cyc.
#define A_BYTES    (128 * 128)
#define B_BYTES    (128 * 128)
#define STAGE      (A_BYTES + B_BYTES)   // 32768
#define NSTAGE     3
#define GEMM_SMEM  (NSTAGE * STAGE + 1024)
#define KITERS     16

__device__ __forceinline__ void load_tile(uint32_t sbase, int m0, int n0, int it, int tid) {
    const int kc = it << 6;
#pragma unroll
    for (int i = 0; i < 8; i++) {            // A: 128 rows x 8 16B-groups
        int slot = tid + 128 * i;
        int row = slot >> 3, grp = slot & 7;
        const __half* g = g_Xh + (size_t)(m0 + row) * DIM + kc + grp * 8;
        cp_async16(sbase + sw128((uint32_t)(row * 128 + grp * 16)), g);
    }
#pragma unroll
    for (int i = 0; i < 8; i++) {            // B: 128 rows x 8 16B-groups
        int slot = tid + 128 * i;
        int row = slot >> 3, grp = slot & 7;
        const __half* g = g_Wf + (size_t)(n0 + row) * DIM + kc + grp * 8;
        cp_async16(sbase + A_BYTES + sw128((uint32_t)(row * 128 + grp * 16)), g);
    }
}

__global__ __launch_bounds__(128, 2)
void gemm_mma_kernel(const float* __restrict__ bz, const float* __restrict__ bh) {
    extern __shared__ char smem_raw[];
    const uint32_t sb = (smem_u32(smem_raw) + 1023u) & ~1023u;
    const int tid = threadIdx.x;
    const int lane = tid & 31;
    const int wid = tid >> 5;
    const int wm = wid & 1;                  // 2 warps along M (64 rows each)
    const int wn = wid >> 1;                 // 2 warps along N (64 cols each)
    const int m0 = blockIdx.y * 128;
    const int n0 = blockIdx.x * 128;

    float acc[4][8][4];
#pragma unroll
    for (int i = 0; i < 4; i++)
#pragma unroll
        for (int j = 0; j < 8; j++)
#pragma unroll
            for (int k = 0; k < 4; k++) acc[i][j][k] = 0.0f;

    load_tile(sb, m0, n0, 0, tid); CP_COMMIT();
    load_tile(sb + STAGE, m0, n0, 1, tid); CP_COMMIT();

    const int arow = wm * 64 + (lane & 15);          // + mt*16
    const uint32_t akhi = (uint32_t)((lane >> 4) << 4);
    const int brow = wn * 64 + (lane & 7) + ((lane >> 4) << 3);   // + jp*16
    const uint32_t bkhi = (uint32_t)(((lane >> 3) & 1) << 4);

    for (int it = 0; it < KITERS; it++) {
        const uint32_t cur = sb + (uint32_t)(it % NSTAGE) * STAGE;
        if (it < KITERS - 1) cp_wait<1>(); else cp_wait<0>();
        __syncthreads();
        if (it + 2 < KITERS) { load_tile(sb + (uint32_t)((it + 2) % NSTAGE) * STAGE, m0, n0, it + 2, tid); CP_COMMIT(); }

        const uint32_t sA = cur, sB = cur + A_BYTES;
#pragma unroll
        for (int ks = 0; ks < 4; ks++) {
            const uint32_t kb = (uint32_t)(ks * 32);
            uint32_t a[4][4], b[4][4];
#pragma unroll
            for (int mt = 0; mt < 4; mt++) {
                const int r = arow + mt * 16;
                const uint32_t addr = sA + (uint32_t)(r * 128) + ((kb + akhi) ^ (uint32_t)((r & 7) << 4));
                LDSM_X4(a[mt][0], a[mt][1], a[mt][2], a[mt][3], addr);
            }
#pragma unroll
            for (int jp = 0; jp < 4; jp++) {
                const int r = brow + jp * 16;
                const uint32_t addr = sB + (uint32_t)(r * 128) + ((kb + bkhi) ^ (uint32_t)((r & 7) << 4));
                LDSM_X4(b[jp][0], b[jp][1], b[jp][2], b[jp][3], addr);
            }
#pragma unroll
            for (int mt = 0; mt < 4; mt++)
#pragma unroll
                for (int jt = 0; jt < 8; jt++) {
                    const int jp = jt >> 1, h = (jt & 1) * 2;
                    MMA16816(acc[mt][jt], a[mt], b[jp][h], b[jp][h + 1]);
                }
        }
    }

    // Epilogue: bias add (+ sigmoid for z half) + store fp16
    const int gq = lane >> 2, tq = lane & 3;
    const int ncol0 = n0 + wn * 64;
    const bool isz = (n0 < DIM);
    const float* biasp = isz ? (bz + ncol0) : (bh + (ncol0 - DIM));
#pragma unroll
    for (int mt = 0; mt < 4; mt++) {
        const int r0 = m0 + wm * 64 + mt * 16 + gq;
#pragma unroll
        for (int jt = 0; jt < 8; jt++) {
            const int c = jt * 8 + tq * 2;
            const float b0 = biasp[c], b1 = biasp[c + 1];
            float v00 = acc[mt][jt][0] + b0, v01 = acc[mt][jt][1] + b1;
            float v10 = acc[mt][jt][2] + b0, v11 = acc[mt][jt][3] + b1;
            if (isz) {
                v00 = 1.0f / (1.0f + expf(-v00));
                v01 = 1.0f / (1.0f + expf(-v01));
                v10 = 1.0f / (1.0f + expf(-v10));
                v11 = 1.0f / (1.0f + expf(-v11));
            }
            *reinterpret_cast<__half2*>(g_preh + (size_t)r0 * NTOT + ncol0 + c) =
                __floats2half2_rn(v00, v01);
            *reinterpret_cast<__half2*>(g_preh + (size_t)(r0 + 8) * NTOT + ncol0 + c) =
                __floats2half2_rn(v10, v11);
        }
    }
}

// ---------------- scan (3-phase chunked, CHUNK=16, fp16 in) ----------------
__global__ __launch_bounds__(128)
void scanA_kernel() {
    const int bid = blockIdx.x;              // b(4) x c(256) = 1024 blocks
    const int c = bid & (NCH - 1);
    const int b = bid >> 8;
    const int d8 = threadIdx.x * 8;
    const __half* p = g_preh + (size_t)(b * TLEN + c * CHUNK) * NTOT + d8;
    float h[8], pr[8];
#pragma unroll
    for (int i = 0; i < 8; i++) { h[i] = 0.f; pr[i] = 1.f; }
#pragma unroll 4
    for (int t = 0; t < CHUNK; t++) {
        uint4 zr = *reinterpret_cast<const uint4*>(p);
        uint4 hr = *reinterpret_cast<const uint4*>(p + 1024);
        const uint32_t* zw = &zr.x;
        const uint32_t* hw = &hr.x;
#pragma unroll
        for (int q = 0; q < 4; q++) {
            float2 z2 = __half22float2(*reinterpret_cast<const __half2*>(&zw[q]));
            float2 t2 = __half22float2(*reinterpret_cast<const __half2*>(&hw[q]));
            float a0 = 1.0f - z2.x + 1e-8f, a1 = 1.0f - z2.y + 1e-8f;
            h[q * 2 + 0] = fmaf(a0, h[q * 2 + 0], z2.x * t2.x); pr[q * 2 + 0] *= a0;
            h[q * 2 + 1] = fmaf(a1, h[q * 2 + 1], z2.y * t2.y); pr[q * 2 + 1] *= a1;
        }
        p += NTOT;
    }
    const size_t o = (size_t)(b * NCH + c) * DIM + d8;
#pragma unroll
    for (int q = 0; q < 2; q++) {
        float4 pa = { pr[q * 4], pr[q * 4 + 1], pr[q * 4 + 2], pr[q * 4 + 3] };
        float4 ha = { h[q * 4], h[q * 4 + 1], h[q * 4 + 2], h[q * 4 + 3] };
        *reinterpret_cast<float4*>(g_aggA + o + q * 4) = pa;
        *reinterpret_cast<float4*>(g_aggH + o + q * 4) = ha;
    }
}

__global__ __launch_bounds__(256)
void scanB_kernel() {
    const int g = blockIdx.x * blockDim.x + threadIdx.x;   // 0..4095
    const int b = g >> 10;
    const int d = g & 1023;
    float carry = 0.0f;
#pragma unroll 4
    for (int c = 0; c < NCH; c++) {
        const size_t idx = (size_t)(b * NCH + c) * DIM + d;
        g_carry[idx] = carry;
        carry = fmaf(g_aggA[idx], carry, g_aggH[idx]);
    }
}

__global__ __launch_bounds__(128)
void scanC_kernel(float* __restrict__ out) {
    const int bid = blockIdx.x;
    const int c = bid & (NCH - 1);
    const int b = bid >> 8;
    const int d8 = threadIdx.x * 8;
    const __half* p = g_preh + (size_t)(b * TLEN + c * CHUNK) * NTOT + d8;
    float* o = out + (size_t)(b * TLEN + c * CHUNK) * DIM + d8;
    const size_t ci = (size_t)(b * NCH + c) * DIM + d8;
    float h[8];
    {
        float4 c0 = *reinterpret_cast<const float4*>(g_carry + ci);
        float4 c1 = *reinterpret_cast<const float4*>(g_carry + ci + 4);
        h[0] = c0.x; h[1] = c0.y; h[2] = c0.z; h[3] = c0.w;
        h[4] = c1.x; h[5] = c1.y; h[6] = c1.z; h[7] = c1.w;
    }
#pragma unroll 4
    for (int t = 0; t < CHUNK; t++) {
        uint4 zr = *reinterpret_cast<const uint4*>(p);
        uint4 hr = *reinterpret_cast<const uint4*>(p + 1024);
        const uint32_t* zw = &zr.x;
        const uint32_t* hw = &hr.x;
#pragma unroll
        for (int q = 0; q < 4; q++) {
            float2 z2 = __half22float2(*reinterpret_cast<const __half2*>(&zw[q]));
            float2 t2 = __half22float2(*reinterpret_cast<const __half2*>(&hw[q]));
            float a0 = 1.0f - z2.x + 1e-8f, a1 = 1.0f - z2.y + 1e-8f;
            h[q * 2 + 0] = fmaf(a0, h[q * 2 + 0], z2.x * t2.x);
            h[q * 2 + 1] = fmaf(a1, h[q * 2 + 1], z2.y * t2.y);
        }
        float4 w0 = { h[0], h[1], h[2], h[3] };
        float4 w1 = { h[4], h[5], h[6], h[7] };
        *reinterpret_cast<float4*>(o)     = w0;
        *reinterpret_cast<float4*>(o + 4) = w1;
        p += NTOT;
        o += DIM;
    }
}

// ---------------- launch ----------------------------------------------------
extern "C" void kernel_launch(void* const* d_in, const int* in_sizes, int n_in,
                              void* d_out, int out_size) {
    const float* x  = (const float*)d_in[0];
    const float* Wz = (const float*)d_in[1];
    const float* bz = (const float*)d_in[2];
    const float* Wh = (const float*)d_in[3];
    const float* bh = (const float*)d_in[4];
    float* out = (float*)d_out;

    cudaFuncSetAttribute(gemm_mma_kernel, cudaFuncAttributeMaxDynamicSharedMemorySize, GEMM_SMEM);

    convert_w_kernel<<<((size_t)NTOT * DIM / 4) / 256, 256>>>(Wz, Wh);
    convert_x_kernel<<<((size_t)MTOT * DIM / 4) / 256, 256>>>(x);
    gemm_mma_kernel<<<dim3(NTOT / 128, MTOT / 128), 128, GEMM_SMEM>>>(bz, bh);
    scanA_kernel<<<BATCH * NCH, 128>>>();
    scanB_kernel<<<(BATCH * DIM) / 256, 256>>>();
    scanC_kernel<<<BATCH * NCH, 128>>>(out);
}

// round 10
// speedup vs baseline: 1.0332x; 1.0332x over previous
#include <cuda_runtime.h>
#include <cuda_fp16.h>
#include <cstdint>
#include <math.h>

#define BATCH 4
#define TLEN  4096
#define DIM   1024
#define MTOT  (BATCH * TLEN)     // 16384
#define NTOT  (2 * DIM)          // 2048 (z cols | h cols)

// ---------------- scratch (device globals; no allocation allowed) ----------
__device__ __half g_Xh[(size_t)MTOT * DIM];     // [M, 1024] fp16
__device__ __half g_Wf[(size_t)NTOT * DIM];     // [2048 rows: Wz|Wh, 1024] fp16
__device__ __half g_preh[(size_t)MTOT * NTOT];  // z (post-sigmoid) | h_tilde, fp16
#define CHUNK 16
#define NCH   (TLEN / CHUNK)     // 256
__device__ float g_aggA[BATCH * NCH * DIM];
__device__ float g_aggH[BATCH * NCH * DIM];
__device__ float g_carry[BATCH * NCH * DIM];

// ---------------- PTX helpers (compute_103-safe only) ----------------------
__device__ __forceinline__ uint32_t smem_u32(const void* p) {
    uint32_t a;
    asm("{ .reg .u64 t; cvta.to.shared.u64 t, %1; cvt.u32.u64 %0, t; }" : "=r"(a) : "l"(p));
    return a;
}
__device__ __forceinline__ uint32_t sw128(uint32_t o) { return o ^ ((o >> 3) & 0x70); }

__device__ __forceinline__ void cp_async16(uint32_t s, const void* g) {
    asm volatile("cp.async.cg.shared.global [%0], [%1], 16;" :: "r"(s), "l"(g));
}
#define CP_COMMIT() asm volatile("cp.async.commit_group;" ::: "memory")
template <int N> __device__ __forceinline__ void cp_wait() {
    asm volatile("cp.async.wait_group %0;" :: "n"(N) : "memory");
}

#define LDSM_X4(r0, r1, r2, r3, addr) \
    asm volatile("ldmatrix.sync.aligned.m8n8.x4.shared.b16 {%0,%1,%2,%3}, [%4];" \
        : "=r"(r0), "=r"(r1), "=r"(r2), "=r"(r3) : "r"(addr))

#define MMA16816(d, a, b0, b1) \
    asm volatile("mma.sync.aligned.m16n8k16.row.col.f32.f16.f16.f32 " \
        "{%0,%1,%2,%3}, {%4,%5,%6,%7}, {%8,%9}, {%0,%1,%2,%3};" \
        : "+f"((d)[0]), "+f"((d)[1]), "+f"((d)[2]), "+f"((d)[3]) \
        : "r"((a)[0]), "r"((a)[1]), "r"((a)[2]), "r"((a)[3]), "r"(b0), "r"(b1))

// ---------------- conversion kernels ---------------------------------------
__device__ __forceinline__ uint2 pack4h(float a, float b, float c, float d) {
    __half2 p0 = __floats2half2_rn(a, b);
    __half2 p1 = __floats2half2_rn(c, d);
    uint2 r;
    r.x = *reinterpret_cast<uint32_t*>(&p0);
    r.y = *reinterpret_cast<uint32_t*>(&p1);
    return r;
}

__global__ void convert_x_kernel(const float* __restrict__ x) {
    size_t i4 = (size_t)blockIdx.x * blockDim.x + threadIdx.x;
    size_t e = i4 * 4;
    float4 v = *reinterpret_cast<const float4*>(x + e);
    *reinterpret_cast<uint2*>(g_Xh + e) = pack4h(v.x, v.y, v.z, v.w);
}

__global__ void convert_w_kernel(const float* __restrict__ Wz, const float* __restrict__ Wh) {
    size_t i4 = (size_t)blockIdx.x * blockDim.x + threadIdx.x;
    size_t e = i4 * 4;
    const float* src = (e < (size_t)DIM * DIM) ? (Wz + e) : (Wh + (e - (size_t)DIM * DIM));
    float4 v = *reinterpret_cast<const float4*>(src);
    *reinterpret_cast<uint2*>(g_Wf + e) = pack4h(v.x, v.y, v.z, v.w);
}

// ---------------- mma.sync fp16 GEMM (R8 config: 8 warps, 32x64 tile) ------
#define A_BYTES    (128 * 128)
#define B_BYTES    (128 * 128)
#define STAGE      (A_BYTES + B_BYTES)   // 32768
#define NSTAGE     3
#define GEMM_SMEM  (NSTAGE * STAGE + 1024)
#define KITERS     16

__device__ __forceinline__ void load_tile(uint32_t sbase, int m0, int n0, int it, int tid) {
    const int kc = it << 6;
#pragma unroll
    for (int i = 0; i < 4; i++) {            // A: 128 rows x 8 16B-groups
        int slot = tid + 256 * i;
        int row = slot >> 3, grp = slot & 7;
        const __half* g = g_Xh + (size_t)(m0 + row) * DIM + kc + grp * 8;
        cp_async16(sbase + sw128((uint32_t)(row * 128 + grp * 16)), g);
    }
#pragma unroll
    for (int i = 0; i < 4; i++) {            // B: 128 rows x 8 16B-groups
        int slot = tid + 256 * i;
        int row = slot >> 3, grp = slot & 7;
        const __half* g = g_Wf + (size_t)(n0 + row) * DIM + kc + grp * 8;
        cp_async16(sbase + A_BYTES + sw128((uint32_t)(row * 128 + grp * 16)), g);
    }
}

__global__ __launch_bounds__(256, 2)
void gemm_mma_kernel(const float* __restrict__ bz, const float* __restrict__ bh) {
    extern __shared__ char smem_raw[];
    const uint32_t sb = (smem_u32(smem_raw) + 1023u) & ~1023u;
    const int tid = threadIdx.x;
    const int lane = tid & 31;
    const int wid = tid >> 5;
    const int wm = wid & 3;
    const int wn = wid >> 2;
    const int m0 = blockIdx.y * 128;
    const int n0 = blockIdx.x * 128;

    float acc[2][8][4];
#pragma unroll
    for (int i = 0; i < 2; i++)
#pragma unroll
        for (int j = 0; j < 8; j++)
#pragma unroll
            for (int k = 0; k < 4; k++) acc[i][j][k] = 0.0f;

    load_tile(sb, m0, n0, 0, tid); CP_COMMIT();
    load_tile(sb + STAGE, m0, n0, 1, tid); CP_COMMIT();

    const int arow = wm * 32 + (lane & 15);
    const uint32_t akhi = (uint32_t)((lane >> 4) << 4);
    const int brow = wn * 64 + (lane & 7) + ((lane >> 4) << 3);
    const uint32_t bkhi = (uint32_t)(((lane >> 3) & 1) << 4);

    for (int it = 0; it < KITERS; it++) {
        const uint32_t cur = sb + (uint32_t)(it % NSTAGE) * STAGE;
        if (it < KITERS - 1) cp_wait<1>(); else cp_wait<0>();
        __syncthreads();
        if (it + 2 < KITERS) { load_tile(sb + (uint32_t)((it + 2) % NSTAGE) * STAGE, m0, n0, it + 2, tid); CP_COMMIT(); }

        const uint32_t sA = cur, sB = cur + A_BYTES;
#pragma unroll
        for (int ks = 0; ks < 4; ks++) {
            const uint32_t kb = (uint32_t)(ks * 32);
            uint32_t a[2][4], b[4][4];
#pragma unroll
            for (int mt = 0; mt < 2; mt++) {
                const int r = arow + mt * 16;
                const uint32_t addr = sA + (uint32_t)(r * 128) + ((kb + akhi) ^ (uint32_t)((r & 7) << 4));
                LDSM_X4(a[mt][0], a[mt][1], a[mt][2], a[mt][3], addr);
            }
#pragma unroll
            for (int jp = 0; jp < 4; jp++) {
                const int r = brow + jp * 16;
                const uint32_t addr = sB + (uint32_t)(r * 128) + ((kb + bkhi) ^ (uint32_t)((r & 7) << 4));
                LDSM_X4(b[jp][0], b[jp][1], b[jp][2], b[jp][3], addr);
            }
#pragma unroll
            for (int mt = 0; mt < 2; mt++)
#pragma unroll
                for (int jt = 0; jt < 8; jt++) {
                    const int jp = jt >> 1, h = (jt & 1) * 2;
                    MMA16816(acc[mt][jt], a[mt], b[jp][h], b[jp][h + 1]);
                }
        }
    }

    // Epilogue: bias add (+ sigmoid for z half) + store fp16
    const int gq = lane >> 2, tq = lane & 3;
    const int ncol0 = n0 + wn * 64;
    const bool isz = (n0 < DIM);
    const float* biasp = isz ? (bz + ncol0) : (bh + (ncol0 - DIM));
#pragma unroll
    for (int mt = 0; mt < 2; mt++) {
        const int r0 = m0 + wm * 32 + mt * 16 + gq;
#pragma unroll
        for (int jt = 0; jt < 8; jt++) {
            const int c = jt * 8 + tq * 2;
            const float b0 = biasp[c], b1 = biasp[c + 1];
            float v00 = acc[mt][jt][0] + b0, v01 = acc[mt][jt][1] + b1;
            float v10 = acc[mt][jt][2] + b0, v11 = acc[mt][jt][3] + b1;
            if (isz) {
                v00 = 1.0f / (1.0f + expf(-v00));
                v01 = 1.0f / (1.0f + expf(-v01));
                v10 = 1.0f / (1.0f + expf(-v10));
                v11 = 1.0f / (1.0f + expf(-v11));
            }
            *reinterpret_cast<__half2*>(g_preh + (size_t)r0 * NTOT + ncol0 + c) =
                __floats2half2_rn(v00, v01);
            *reinterpret_cast<__half2*>(g_preh + (size_t)(r0 + 8) * NTOT + ncol0 + c) =
                __floats2half2_rn(v10, v11);
        }
    }
}

// ---------------- scan (3-phase chunked, CHUNK=16, fp16 in) ----------------
__global__ __launch_bounds__(128)
void scanA_kernel() {
    const int bid = blockIdx.x;              // b(4) x c(256) = 1024 blocks
    const int c = bid & (NCH - 1);
    const int b = bid >> 8;
    const int d8 = threadIdx.x * 8;
    const __half* p = g_preh + (size_t)(b * TLEN + c * CHUNK) * NTOT + d8;
    float h[8], pr[8];
#pragma unroll
    for (int i = 0; i < 8; i++) { h[i] = 0.f; pr[i] = 1.f; }
#pragma unroll 4
    for (int t = 0; t < CHUNK; t++) {
        uint4 zr = *reinterpret_cast<const uint4*>(p);
        uint4 hr = *reinterpret_cast<const uint4*>(p + 1024);
        const uint32_t* zw = &zr.x;
        const uint32_t* hw = &hr.x;
#pragma unroll
        for (int q = 0; q < 4; q++) {
            float2 z2 = __half22float2(*reinterpret_cast<const __half2*>(&zw[q]));
            float2 t2 = __half22float2(*reinterpret_cast<const __half2*>(&hw[q]));
            float a0 = 1.0f - z2.x + 1e-8f, a1 = 1.0f - z2.y + 1e-8f;
            h[q * 2 + 0] = fmaf(a0, h[q * 2 + 0], z2.x * t2.x); pr[q * 2 + 0] *= a0;
            h[q * 2 + 1] = fmaf(a1, h[q * 2 + 1], z2.y * t2.y); pr[q * 2 + 1] *= a1;
        }
        p += NTOT;
    }
    const size_t o = (size_t)(b * NCH + c) * DIM + d8;
#pragma unroll
    for (int q = 0; q < 2; q++) {
        float4 pa = { pr[q * 4], pr[q * 4 + 1], pr[q * 4 + 2], pr[q * 4 + 3] };
        float4 ha = { h[q * 4], h[q * 4 + 1], h[q * 4 + 2], h[q * 4 + 3] };
        *reinterpret_cast<float4*>(g_aggA + o + q * 4) = pa;
        *reinterpret_cast<float4*>(g_aggH + o + q * 4) = ha;
    }
}

__global__ __launch_bounds__(256)
void scanB_kernel() {
    const int g = blockIdx.x * blockDim.x + threadIdx.x;   // 0..4095
    const int b = g >> 10;
    const int d = g & 1023;
    float carry = 0.0f;
#pragma unroll 4
    for (int c = 0; c < NCH; c++) {
        const size_t idx = (size_t)(b * NCH + c) * DIM + d;
        g_carry[idx] = carry;
        carry = fmaf(g_aggA[idx], carry, g_aggH[idx]);
    }
}

__global__ __launch_bounds__(128)
void scanC_kernel(float* __restrict__ out) {
    const int bid = blockIdx.x;
    const int c = bid & (NCH - 1);
    const int b = bid >> 8;
    const int d8 = threadIdx.x * 8;
    const __half* p = g_preh + (size_t)(b * TLEN + c * CHUNK) * NTOT + d8;
    float* o = out + (size_t)(b * TLEN + c * CHUNK) * DIM + d8;
    const size_t ci = (size_t)(b * NCH + c) * DIM + d8;
    float h[8];
    {
        float4 c0 = *reinterpret_cast<const float4*>(g_carry + ci);
        float4 c1 = *reinterpret_cast<const float4*>(g_carry + ci + 4);
        h[0] = c0.x; h[1] = c0.y; h[2] = c0.z; h[3] = c0.w;
        h[4] = c1.x; h[5] = c1.y; h[6] = c1.z; h[7] = c1.w;
    }
#pragma unroll 4
    for (int t = 0; t < CHUNK; t++) {
        uint4 zr = *reinterpret_cast<const uint4*>(p);
        uint4 hr = *reinterpret_cast<const uint4*>(p + 1024);
        const uint32_t* zw = &zr.x;
        const uint32_t* hw = &hr.x;
#pragma unroll
        for (int q = 0; q < 4; q++) {
            float2 z2 = __half22float2(*reinterpret_cast<const __half2*>(&zw[q]));
            float2 t2 = __half22float2(*reinterpret_cast<const __half2*>(&hw[q]));
            float a0 = 1.0f - z2.x + 1e-8f, a1 = 1.0f - z2.y + 1e-8f;
            h[q * 2 + 0] = fmaf(a0, h[q * 2 + 0], z2.x * t2.x);
            h[q * 2 + 1] = fmaf(a1, h[q * 2 + 1], z2.y * t2.y);
        }
        float4 w0 = { h[0], h[1], h[2], h[3] };
        float4 w1 = { h[4], h[5], h[6], h[7] };
        *reinterpret_cast<float4*>(o)     = w0;
        *reinterpret_cast<float4*>(o + 4) = w1;
        p += NTOT;
        o += DIM;
    }
}

// ---------------- launch ----------------------------------------------------
extern "C" void kernel_launch(void* const* d_in, const int* in_sizes, int n_in,
                              void* d_out, int out_size) {
    const float* x  = (const float*)d_in[0];
    const float* Wz = (const float*)d_in[1];
    const float* bz = (const float*)d_in[2];
    const float* Wh = (const float*)d_in[3];
    const float* bh = (const float*)d_in[4];
    float* out = (float*)d_out;

    cudaFuncSetAttribute(gemm_mma_kernel, cudaFuncAttributeMaxDynamicSharedMemorySize, GEMM_SMEM);

    convert_w_kernel<<<((size_t)NTOT * DIM / 4) / 256, 256>>>(Wz, Wh);
    convert_x_kernel<<<((size_t)MTOT * DIM / 4) / 256, 256>>>(x);
    gemm_mma_kernel<<<dim3(NTOT / 128, MTOT / 128), 256, GEMM_SMEM>>>(bz, bh);
    scanA_kernel<<<BATCH * NCH, 128>>>();
    scanB_kernel<<<(BATCH * DIM) / 256, 256>>>();
    scanC_kernel<<<BATCH * NCH, 128>>>(out);
}

// round 11
// speedup vs baseline: 1.2042x; 1.1655x over previous
#include <cuda_runtime.h>
#include <cuda_fp16.h>
#include <cstdint>
#include <math.h>

#define BATCH 4
#define TLEN  4096
#define DIM   1024
#define MTOT  (BATCH * TLEN)     // 16384
#define NTOT  (2 * DIM)          // 2048 (z cols | h cols)

// ---------------- scratch (device globals; no allocation allowed) ----------
__device__ __half g_Xh[(size_t)MTOT * DIM];     // [M, 1024] fp16
__device__ __half g_Wf[(size_t)NTOT * DIM];     // [2048 rows: Wz|Wh, 1024] fp16
__device__ __half g_preh[(size_t)MTOT * NTOT];  // z (post-sigmoid) | h_tilde, fp16
#define CHUNK 32
#define NCH   (TLEN / CHUNK)     // 128
__device__ float g_aggA[BATCH * NCH * DIM];
__device__ float g_aggH[BATCH * NCH * DIM];
__device__ float g_carry[BATCH * NCH * DIM];

// ---------------- PTX helpers (compute_103-safe only) ----------------------
__device__ __forceinline__ uint32_t smem_u32(const void* p) {
    uint32_t a;
    asm("{ .reg .u64 t; cvta.to.shared.u64 t, %1; cvt.u32.u64 %0, t; }" : "=r"(a) : "l"(p));
    return a;
}
__device__ __forceinline__ uint32_t sw128(uint32_t o) { return o ^ ((o >> 3) & 0x70); }

__device__ __forceinline__ void cp_async16(uint32_t s, const void* g) {
    asm volatile("cp.async.cg.shared.global [%0], [%1], 16;" :: "r"(s), "l"(g));
}
#define CP_COMMIT() asm volatile("cp.async.commit_group;" ::: "memory")
template <int N> __device__ __forceinline__ void cp_wait() {
    asm volatile("cp.async.wait_group %0;" :: "n"(N) : "memory");
}

#define LDSM_X4(r0, r1, r2, r3, addr) \
    asm volatile("ldmatrix.sync.aligned.m8n8.x4.shared.b16 {%0,%1,%2,%3}, [%4];" \
        : "=r"(r0), "=r"(r1), "=r"(r2), "=r"(r3) : "r"(addr))

#define MMA16816(d, a, b0, b1) \
    asm volatile("mma.sync.aligned.m16n8k16.row.col.f32.f16.f16.f32 " \
        "{%0,%1,%2,%3}, {%4,%5,%6,%7}, {%8,%9}, {%0,%1,%2,%3};" \
        : "+f"((d)[0]), "+f"((d)[1]), "+f"((d)[2]), "+f"((d)[3]) \
        : "r"((a)[0]), "r"((a)[1]), "r"((a)[2]), "r"((a)[3]), "r"(b0), "r"(b1))

// ---------------- conversion kernels ---------------------------------------
__device__ __forceinline__ uint2 pack4h(float a, float b, float c, float d) {
    __half2 p0 = __floats2half2_rn(a, b);
    __half2 p1 = __floats2half2_rn(c, d);
    uint2 r;
    r.x = *reinterpret_cast<uint32_t*>(&p0);
    r.y = *reinterpret_cast<uint32_t*>(&p1);
    return r;
}

__global__ void convert_x_kernel(const float* __restrict__ x) {
    size_t i4 = (size_t)blockIdx.x * blockDim.x + threadIdx.x;
    size_t e = i4 * 4;
    float4 v = *reinterpret_cast<const float4*>(x + e);
    *reinterpret_cast<uint2*>(g_Xh + e) = pack4h(v.x, v.y, v.z, v.w);
}

__global__ void convert_w_kernel(const float* __restrict__ Wz, const float* __restrict__ Wh) {
    size_t i4 = (size_t)blockIdx.x * blockDim.x + threadIdx.x;
    size_t e = i4 * 4;
    const float* src = (e < (size_t)DIM * DIM) ? (Wz + e) : (Wh + (e - (size_t)DIM * DIM));
    float4 v = *reinterpret_cast<const float4*>(src);
    *reinterpret_cast<uint2*>(g_Wf + e) = pack4h(v.x, v.y, v.z, v.w);
}

// ---------------- mma.sync fp16 GEMM (R8 config: 8 warps, 32x64 tile) ------
#define A_BYTES    (128 * 128)
#define B_BYTES    (128 * 128)
#define STAGE      (A_BYTES + B_BYTES)   // 32768
#define NSTAGE     3
#define GEMM_SMEM  (NSTAGE * STAGE + 1024)
#define KITERS     16

__device__ __forceinline__ void load_tile(uint32_t sbase, int m0, int n0, int it, int tid) {
    const int kc = it << 6;
#pragma unroll
    for (int i = 0; i < 4; i++) {            // A: 128 rows x 8 16B-groups
        int slot = tid + 256 * i;
        int row = slot >> 3, grp = slot & 7;
        const __half* g = g_Xh + (size_t)(m0 + row) * DIM + kc + grp * 8;
        cp_async16(sbase + sw128((uint32_t)(row * 128 + grp * 16)), g);
    }
#pragma unroll
    for (int i = 0; i < 4; i++) {            // B: 128 rows x 8 16B-groups
        int slot = tid + 256 * i;
        int row = slot >> 3, grp = slot & 7;
        const __half* g = g_Wf + (size_t)(n0 + row) * DIM + kc + grp * 8;
        cp_async16(sbase + A_BYTES + sw128((uint32_t)(row * 128 + grp * 16)), g);
    }
}

__global__ __launch_bounds__(256, 2)
void gemm_mma_kernel(const float* __restrict__ bz, const float* __restrict__ bh) {
    extern __shared__ char smem_raw[];
    const uint32_t sb = (smem_u32(smem_raw) + 1023u) & ~1023u;
    const int tid = threadIdx.x;
    const int lane = tid & 31;
    const int wid = tid >> 5;
    const int wm = wid & 3;
    const int wn = wid >> 2;
    const int m0 = blockIdx.y * 128;
    const int n0 = blockIdx.x * 128;

    float acc[2][8][4];
#pragma unroll
    for (int i = 0; i < 2; i++)
#pragma unroll
        for (int j = 0; j < 8; j++)
#pragma unroll
            for (int k = 0; k < 4; k++) acc[i][j][k] = 0.0f;

    load_tile(sb, m0, n0, 0, tid); CP_COMMIT();
    load_tile(sb + STAGE, m0, n0, 1, tid); CP_COMMIT();

    const int arow = wm * 32 + (lane & 15);
    const uint32_t akhi = (uint32_t)((lane >> 4) << 4);
    const int brow = wn * 64 + (lane & 7) + ((lane >> 4) << 3);
    const uint32_t bkhi = (uint32_t)(((lane >> 3) & 1) << 4);

    for (int it = 0; it < KITERS; it++) {
        const uint32_t cur = sb + (uint32_t)(it % NSTAGE) * STAGE;
        if (it < KITERS - 1) cp_wait<1>(); else cp_wait<0>();
        __syncthreads();
        if (it + 2 < KITERS) { load_tile(sb + (uint32_t)((it + 2) % NSTAGE) * STAGE, m0, n0, it + 2, tid); CP_COMMIT(); }

        const uint32_t sA = cur, sB = cur + A_BYTES;
#pragma unroll
        for (int ks = 0; ks < 4; ks++) {
            const uint32_t kb = (uint32_t)(ks * 32);
            uint32_t a[2][4], b[4][4];
#pragma unroll
            for (int mt = 0; mt < 2; mt++) {
                const int r = arow + mt * 16;
                const uint32_t addr = sA + (uint32_t)(r * 128) + ((kb + akhi) ^ (uint32_t)((r & 7) << 4));
                LDSM_X4(a[mt][0], a[mt][1], a[mt][2], a[mt][3], addr);
            }
#pragma unroll
            for (int jp = 0; jp < 4; jp++) {
                const int r = brow + jp * 16;
                const uint32_t addr = sB + (uint32_t)(r * 128) + ((kb + bkhi) ^ (uint32_t)((r & 7) << 4));
                LDSM_X4(b[jp][0], b[jp][1], b[jp][2], b[jp][3], addr);
            }
#pragma unroll
            for (int mt = 0; mt < 2; mt++)
#pragma unroll
                for (int jt = 0; jt < 8; jt++) {
                    const int jp = jt >> 1, h = (jt & 1) * 2;
                    MMA16816(acc[mt][jt], a[mt], b[jp][h], b[jp][h + 1]);
                }
        }
    }

    // Epilogue: bias add (+ sigmoid for z half) + store fp16
    const int gq = lane >> 2, tq = lane & 3;
    const int ncol0 = n0 + wn * 64;
    const bool isz = (n0 < DIM);
    const float* biasp = isz ? (bz + ncol0) : (bh + (ncol0 - DIM));
#pragma unroll
    for (int mt = 0; mt < 2; mt++) {
        const int r0 = m0 + wm * 32 + mt * 16 + gq;
#pragma unroll
        for (int jt = 0; jt < 8; jt++) {
            const int c = jt * 8 + tq * 2;
            const float b0 = biasp[c], b1 = biasp[c + 1];
            float v00 = acc[mt][jt][0] + b0, v01 = acc[mt][jt][1] + b1;
            float v10 = acc[mt][jt][2] + b0, v11 = acc[mt][jt][3] + b1;
            if (isz) {
                v00 = 1.0f / (1.0f + expf(-v00));
                v01 = 1.0f / (1.0f + expf(-v01));
                v10 = 1.0f / (1.0f + expf(-v10));
                v11 = 1.0f / (1.0f + expf(-v11));
            }
            *reinterpret_cast<__half2*>(g_preh + (size_t)r0 * NTOT + ncol0 + c) =
                __floats2half2_rn(v00, v01);
            *reinterpret_cast<__half2*>(g_preh + (size_t)(r0 + 8) * NTOT + ncol0 + c) =
                __floats2half2_rn(v10, v11);
        }
    }
}

// ---------------- scan (3-phase chunked, CHUNK=32, NCH=128, fp16 in) -------
// scanA/scanC: 256 threads/block, 4 channels per thread (8B loads) -> 2x warps
__global__ __launch_bounds__(256)
void scanA_kernel() {
    const int bid = blockIdx.x;              // b(4) x c(128) = 512 blocks
    const int c = bid & (NCH - 1);
    const int b = bid >> 7;
    const int d4 = threadIdx.x * 4;
    const __half* p = g_preh + (size_t)(b * TLEN + c * CHUNK) * NTOT + d4;
    float h[4], pr[4];
#pragma unroll
    for (int i = 0; i < 4; i++) { h[i] = 0.f; pr[i] = 1.f; }
#pragma unroll 8
    for (int t = 0; t < CHUNK; t++) {
        uint2 zr = *reinterpret_cast<const uint2*>(p);
        uint2 hr = *reinterpret_cast<const uint2*>(p + 1024);
        const uint32_t* zw = &zr.x;
        const uint32_t* hw = &hr.x;
#pragma unroll
        for (int q = 0; q < 2; q++) {
            float2 z2 = __half22float2(*reinterpret_cast<const __half2*>(&zw[q]));
            float2 t2 = __half22float2(*reinterpret_cast<const __half2*>(&hw[q]));
            float a0 = 1.0f - z2.x + 1e-8f, a1 = 1.0f - z2.y + 1e-8f;
            h[q * 2 + 0] = fmaf(a0, h[q * 2 + 0], z2.x * t2.x); pr[q * 2 + 0] *= a0;
            h[q * 2 + 1] = fmaf(a1, h[q * 2 + 1], z2.y * t2.y); pr[q * 2 + 1] *= a1;
        }
        p += NTOT;
    }
    const size_t o = (size_t)(b * NCH + c) * DIM + d4;
    float4 pa = { pr[0], pr[1], pr[2], pr[3] };
    float4 ha = { h[0], h[1], h[2], h[3] };
    *reinterpret_cast<float4*>(g_aggA + o) = pa;
    *reinterpret_cast<float4*>(g_aggH + o) = ha;
}

__global__ __launch_bounds__(256)
void scanB_kernel() {
    const int g = blockIdx.x * blockDim.x + threadIdx.x;   // 0..4095
    const int b = g >> 10;
    const int d = g & 1023;
    float carry = 0.0f;
#pragma unroll 4
    for (int c = 0; c < NCH; c++) {
        const size_t idx = (size_t)(b * NCH + c) * DIM + d;
        g_carry[idx] = carry;
        carry = fmaf(g_aggA[idx], carry, g_aggH[idx]);
    }
}

__global__ __launch_bounds__(256)
void scanC_kernel(float* __restrict__ out) {
    const int bid = blockIdx.x;
    const int c = bid & (NCH - 1);
    const int b = bid >> 7;
    const int d4 = threadIdx.x * 4;
    const __half* p = g_preh + (size_t)(b * TLEN + c * CHUNK) * NTOT + d4;
    float* o = out + (size_t)(b * TLEN + c * CHUNK) * DIM + d4;
    float h[4];
    {
        float4 c0 = *reinterpret_cast<const float4*>(g_carry + (size_t)(b * NCH + c) * DIM + d4);
        h[0] = c0.x; h[1] = c0.y; h[2] = c0.z; h[3] = c0.w;
    }
#pragma unroll 8
    for (int t = 0; t < CHUNK; t++) {
        uint2 zr = *reinterpret_cast<const uint2*>(p);
        uint2 hr = *reinterpret_cast<const uint2*>(p + 1024);
        const uint32_t* zw = &zr.x;
        const uint32_t* hw = &hr.x;
#pragma unroll
        for (int q = 0; q < 2; q++) {
            float2 z2 = __half22float2(*reinterpret_cast<const __half2*>(&zw[q]));
            float2 t2 = __half22float2(*reinterpret_cast<const __half2*>(&hw[q]));
            float a0 = 1.0f - z2.x + 1e-8f, a1 = 1.0f - z2.y + 1e-8f;
            h[q * 2 + 0] = fmaf(a0, h[q * 2 + 0], z2.x * t2.x);
            h[q * 2 + 1] = fmaf(a1, h[q * 2 + 1], z2.y * t2.y);
        }
        float4 w = { h[0], h[1], h[2], h[3] };
        *reinterpret_cast<float4*>(o) = w;
        p += NTOT;
        o += DIM;
    }
}

// ---------------- launch ----------------------------------------------------
extern "C" void kernel_launch(void* const* d_in, const int* in_sizes, int n_in,
                              void* d_out, int out_size) {
    const float* x  = (const float*)d_in[0];
    const float* Wz = (const float*)d_in[1];
    const float* bz = (const float*)d_in[2];
    const float* Wh = (const float*)d_in[3];
    const float* bh = (const float*)d_in[4];
    float* out = (float*)d_out;

    cudaFuncSetAttribute(gemm_mma_kernel, cudaFuncAttributeMaxDynamicSharedMemorySize, GEMM_SMEM);

    convert_w_kernel<<<((size_t)NTOT * DIM / 4) / 256, 256>>>(Wz, Wh);
    convert_x_kernel<<<((size_t)MTOT * DIM / 4) / 256, 256>>>(x);
    gemm_mma_kernel<<<dim3(NTOT / 128, MTOT / 128), 256, GEMM_SMEM>>>(bz, bh);
    scanA_kernel<<<BATCH * NCH, 256>>>();
    scanB_kernel<<<(BATCH * DIM) / 256, 256>>>();
    scanC_kernel<<<BATCH * NCH, 256>>>(out);
}